// round 9
// baseline (speedup 1.0000x reference)
#include <cuda_runtime.h>
#include <cuda_bf16.h>
#include <cuda_fp16.h>
#include <math.h>
#include <stdint.h>

#define BATCH 2
#define NSEQ  2048
#define DMODEL 1024
#define NLAYER 2
#define VOCAB 50257
#define EPS_F 1e-6f
#define MTOK (BATCH*NSEQ)          // 4096
#define NTILES_H 197               // ceil(50257/256)
#define NPAD_H (NTILES_H*256)      // 50432
#define K3D (3*DMODEL)             // 3072
#define K3N (3*NSEQ)               // 6144
#define QKVLD (3*DMODEL)           // qkv row stride

// ---------------- scratch ----------------
__device__ float g_x  [MTOK*DMODEL];
__device__ float g_qkv[(long)MTOK*3*DMODEL];
__device__ float g_W  [BATCH*DMODEL*DMODEL];   // W2 then G
__device__ float g_ks [BATCH*DMODEL];
__device__ float g_z  [MTOK];

__device__ __align__(128) __nv_bfloat16 g_xs [(long)MTOK*K3D];
__device__ __align__(128) __nv_bfloat16 g_qs [(long)MTOK*K3D];
__device__ __align__(128) __nv_bfloat16 g_kts[(long)BATCH*DMODEL*K3N];
__device__ __align__(128) __nv_bfloat16 g_vts[(long)BATCH*DMODEL*K3N];  // later reused as Gsp
__device__ __align__(128) __nv_bfloat16 g_wbuf[(long)3*DMODEL*K3D];
__device__ __align__(128) __nv_bfloat16 g_Wsp[(long)BATCH*DMODEL*K3D];
__device__ __align__(128) __nv_bfloat16 g_wos[(long)DMODEL*K3D];
__device__ __align__(128) __nv_bfloat16 g_whs[(long)NPAD_H*DMODEL];  // fp16 head weights

// ---------------- helpers ----------------
__device__ __forceinline__ uint32_t smem_u32(const void* p){
    uint32_t a;
    asm("{ .reg .u64 t; cvta.to.shared.u64 t, %1; cvt.u32.u64 %0, t; }" : "=r"(a) : "l"(p));
    return a;
}
__device__ __forceinline__ void ldsm_x4(uint32_t* r, uint32_t addr){
    asm volatile("ldmatrix.sync.aligned.m8n8.x4.shared.b16 {%0,%1,%2,%3}, [%4];"
        : "=r"(r[0]), "=r"(r[1]), "=r"(r[2]), "=r"(r[3]) : "r"(addr));
}
template<int PREC>  // 0 = bf16, 1 = fp16
__device__ __forceinline__ void mma_any(float* d, const uint32_t* a, uint32_t b0, uint32_t b1){
    if (PREC == 0) {
        asm volatile("mma.sync.aligned.m16n8k16.row.col.f32.bf16.bf16.f32 "
            "{%0,%1,%2,%3}, {%4,%5,%6,%7}, {%8,%9}, {%0,%1,%2,%3};"
            : "+f"(d[0]), "+f"(d[1]), "+f"(d[2]), "+f"(d[3])
            : "r"(a[0]), "r"(a[1]), "r"(a[2]), "r"(a[3]), "r"(b0), "r"(b1));
    } else {
        asm volatile("mma.sync.aligned.m16n8k16.row.col.f32.f16.f16.f32 "
            "{%0,%1,%2,%3}, {%4,%5,%6,%7}, {%8,%9}, {%0,%1,%2,%3};"
            : "+f"(d[0]), "+f"(d[1]), "+f"(d[2]), "+f"(d[3])
            : "r"(a[0]), "r"(a[1]), "r"(a[2]), "r"(a[3]), "r"(b0), "r"(b1));
    }
}
__device__ __forceinline__ void cp16(uint32_t saddr, const void* g){
    asm volatile("cp.async.cg.shared.global.L2::128B [%0], [%1], 16;" :: "r"(saddr), "l"(g));
}
#define CP_COMMIT() asm volatile("cp.async.commit_group;" ::: "memory")
#define CP_WAIT(n)  asm volatile("cp.async.wait_group %0;" :: "n"(n) : "memory")

// split fp32 -> (hi, lo) bf16
__device__ __forceinline__ void split8(const float* xv, uint4* hi, uint4* lo){
    __align__(16) __nv_bfloat16 h[8], l[8];
    #pragma unroll
    for (int j = 0; j < 8; j++) {
        h[j] = __float2bfloat16(xv[j]);
        l[j] = __float2bfloat16(xv[j] - __bfloat162float(h[j]));
    }
    *hi = *(const uint4*)h;
    *lo = *(const uint4*)l;
}

// ---------------- pack kernels (interleaved K layout) ------------------------
// K' group g (8 src k) = 24 bf16 at g*24.  A': [hi|hi|lo]  B': [hi|lo|hi]
__global__ void pack_a_direct(const float* __restrict__ src, int Mr, int Kd, int lda,
                              __nv_bfloat16* __restrict__ dst) {
    int kUnits = Kd >> 3;
    long u = (long)blockIdx.x * blockDim.x + threadIdx.x;
    if (u >= (long)Mr * kUnits) return;
    int m  = (int)(u / kUnits);
    int ku = (int)(u % kUnits);
    const float4* s = (const float4*)(src + (long)m * lda + ((long)ku << 3));
    float4 a = s[0], b = s[1];
    float xv[8] = {a.x, a.y, a.z, a.w, b.x, b.y, b.z, b.w};
    uint4 hi, lo; split8(xv, &hi, &lo);
    __nv_bfloat16* base = dst + (long)m * (3*Kd) + (long)ku * 24;
    *(uint4*)(base)      = hi;
    *(uint4*)(base + 8)  = hi;
    *(uint4*)(base + 16) = lo;
}

__global__ void pack_b_direct(const float* __restrict__ src, int Nr, int Kd, int Npad,
                              __nv_bfloat16* __restrict__ dst, long sSrcZ, long sDstZ) {
    int zb = blockIdx.y;
    src += (long)zb * sSrcZ; dst += (long)zb * sDstZ;
    int kUnits = Kd >> 3;
    long u = (long)blockIdx.x * blockDim.x + threadIdx.x;
    if (u >= (long)Npad * kUnits) return;
    int n  = (int)(u / kUnits);
    int ku = (int)(u % kUnits);
    float xv[8] = {0.f,0.f,0.f,0.f,0.f,0.f,0.f,0.f};
    if (n < Nr) {
        const float4* s = (const float4*)(src + (long)n * Kd + ((long)ku << 3));
        float4 a = s[0], b = s[1];
        xv[0]=a.x; xv[1]=a.y; xv[2]=a.z; xv[3]=a.w; xv[4]=b.x; xv[5]=b.y; xv[6]=b.z; xv[7]=b.w;
    }
    uint4 hi, lo; split8(xv, &hi, &lo);
    __nv_bfloat16* base = dst + (long)n * (3*Kd) + (long)ku * 24;
    *(uint4*)(base)      = hi;
    *(uint4*)(base + 8)  = lo;
    *(uint4*)(base + 16) = hi;
}

// fp16 1-term: plain fp32 -> fp16 convert, row-padded to Npad
__global__ void cvt_fp16(const float* __restrict__ src, int Nr, int Kd, int Npad,
                         __half* __restrict__ dst) {
    int kUnits = Kd >> 3;
    long u = (long)blockIdx.x * blockDim.x + threadIdx.x;
    if (u >= (long)Npad * kUnits) return;
    int n  = (int)(u / kUnits);
    int ku = (int)(u % kUnits);
    float xv[8] = {0.f,0.f,0.f,0.f,0.f,0.f,0.f,0.f};
    if (n < Nr) {
        const float4* s = (const float4*)(src + (long)n * Kd + ((long)ku << 3));
        float4 a = s[0], b = s[1];
        xv[0]=a.x; xv[1]=a.y; xv[2]=a.z; xv[3]=a.w; xv[4]=b.x; xv[5]=b.y; xv[6]=b.z; xv[7]=b.w;
    }
    __align__(16) __half h[8];
    #pragma unroll
    for (int j = 0; j < 8; j++) h[j] = __float2half(xv[j]);
    *(uint4*)(dst + (long)n * Kd + ((long)ku << 3)) = *(const uint4*)h;
}

// SMEM-tiled transpose packs: effective OP[r, k] = src[k*ld + r].
template<bool ISA>
__global__ void pack_trans_tiled(const float* __restrict__ src, int ld, int Kd,
                                 __nv_bfloat16* __restrict__ dst, long sSrcZ, long sDstZ) {
    __shared__ float t[64][33];
    int zb = blockIdx.z;
    src += (long)zb * sSrcZ; dst += (long)zb * sDstZ;
    int r0 = blockIdx.x * 32, k0 = blockIdx.y * 64;
    int tid = threadIdx.x;
    #pragma unroll
    for (int i = 0; i < 8; i++) {
        int idx = tid + i * 256;
        int k = idx >> 5, r = idx & 31;
        t[k][r] = src[(long)(k0 + k) * ld + r0 + r];
    }
    __syncthreads();
    int r = tid >> 3, kg = tid & 7;
    float xv[8];
    #pragma unroll
    for (int j = 0; j < 8; j++) xv[j] = t[kg*8 + j][r];
    uint4 hi, lo; split8(xv, &hi, &lo);
    __nv_bfloat16* base = dst + (long)(r0 + r) * (3*Kd) + (long)((k0 >> 3) + kg) * 24;
    if (ISA) {
        *(uint4*)(base)      = hi;
        *(uint4*)(base + 8)  = hi;
        *(uint4*)(base + 16) = lo;
    } else {
        *(uint4*)(base)      = hi;
        *(uint4*)(base + 8)  = lo;
        *(uint4*)(base + 16) = hi;
    }
}

// ---------------- HMMA GEMM ----------------
// C[M,N] = act( A'[M,K3] . B'[N,K3]^T / rowdiv + bias )
// CTA tile 128x256, BK=64, 4-stage cp.async, 8 warps (2x4), warp 64x64.
// act: 0 = linear, 1 = elu+1, 2 = QKV fused (elu+1 for col<2048, segmented bias)
#define STAGES 4
#define A_BYTES 16384
#define STAGE_BYTES 49152
#define GEMM_SMEM (STAGES*STAGE_BYTES)

template<int PREC>
__global__ __launch_bounds__(256, 1)
void hgemm_kernel(const __nv_bfloat16* __restrict__ A,
                  const __nv_bfloat16* __restrict__ B,
                  long sA, long sB,
                  int K3, int N,
                  float* __restrict__ C, int ldc, long sC,
                  const float* __restrict__ bias,
                  const float* __restrict__ bias_b,
                  const float* __restrict__ bias_c,
                  const float* __restrict__ rowdiv, long sR,
                  int act)
{
    extern __shared__ char smem[];
    uint32_t sbase = smem_u32(smem);
    int tid = threadIdx.x;
    int lane = tid & 31, wid = tid >> 5;
    int wm = wid >> 2, wn = wid & 3;     // 2 x 4 warps, each 64x64
    int mBase = blockIdx.x * 128;        // M fastest -> B-tile L2 reuse
    int nBase = blockIdx.y * 256;
    int zb = blockIdx.z;
    A += (long)zb * sA; B += (long)zb * sB; C += (long)zb * sC;
    if (rowdiv) rowdiv += (long)zb * sR;

    const char* aG = (const char*)(A + (long)mBase * K3);
    const char* bG = (const char*)(B + (long)nBase * K3);
    long ldg = (long)K3 * 2;

    int lr = tid >> 3;          // 0..31 row-in-pass
    int la = tid & 7;           // 16B atom in 128B row

    float acc[4][8][4];
    #pragma unroll
    for (int i = 0; i < 4; i++)
        #pragma unroll
        for (int j = 0; j < 8; j++)
            #pragma unroll
            for (int e = 0; e < 4; e++) acc[i][j][e] = 0.f;

    int nK = K3 >> 6;

    #pragma unroll
    for (int s = 0; s < STAGES-1; s++) {
        uint32_t aS = sbase + s*STAGE_BYTES;
        uint32_t bS = aS + A_BYTES;
        const char* ag = aG + (long)s*128;
        const char* bg = bG + (long)s*128;
        #pragma unroll
        for (int p = 0; p < 4; p++) {
            int r = lr + p*32;
            uint32_t so = (uint32_t)r*128 + 16u*(uint32_t)(la ^ (r & 7));
            cp16(aS + so, ag + (long)r*ldg + la*16);
        }
        #pragma unroll
        for (int p = 0; p < 8; p++) {
            int r = lr + p*32;
            uint32_t so = (uint32_t)r*128 + 16u*(uint32_t)(la ^ (r & 7));
            cp16(bS + so, bg + (long)r*ldg + la*16);
        }
        CP_COMMIT();
    }

    for (int i = 0; i < nK; i++) {
        CP_WAIT(STAGES-2);
        __syncthreads();
        int nc = i + STAGES - 1;
        if (nc < nK) {
            int s = nc % STAGES;
            uint32_t aS = sbase + s*STAGE_BYTES;
            uint32_t bS = aS + A_BYTES;
            const char* ag = aG + (long)nc*128;
            const char* bg = bG + (long)nc*128;
            #pragma unroll
            for (int p = 0; p < 4; p++) {
                int r = lr + p*32;
                uint32_t so = (uint32_t)r*128 + 16u*(uint32_t)(la ^ (r & 7));
                cp16(aS + so, ag + (long)r*ldg + la*16);
            }
            #pragma unroll
            for (int p = 0; p < 8; p++) {
                int r = lr + p*32;
                uint32_t so = (uint32_t)r*128 + 16u*(uint32_t)(la ^ (r & 7));
                cp16(bS + so, bg + (long)r*ldg + la*16);
            }
        }
        CP_COMMIT();

        int cs = i % STAGES;
        uint32_t aS = sbase + cs*STAGE_BYTES;
        uint32_t bS = aS + A_BYTES;
        #pragma unroll
        for (int kt = 0; kt < 4; kt++) {
            uint32_t af[4][4];
            #pragma unroll
            for (int mt = 0; mt < 4; mt++) {
                int row = wm*64 + mt*16 + (lane & 15);
                int a = kt*2 + (lane >> 4);
                ldsm_x4(af[mt], aS + (uint32_t)row*128 + 16u*(uint32_t)(a ^ (row & 7)));
            }
            uint32_t bf2[4][4];
            #pragma unroll
            for (int np = 0; np < 4; np++) {
                int row = wn*64 + np*16 + ((lane >> 4) & 1)*8 + (lane & 7);
                int a = kt*2 + ((lane >> 3) & 1);
                ldsm_x4(bf2[np], bS + (uint32_t)row*128 + 16u*(uint32_t)(a ^ (row & 7)));
            }
            #pragma unroll
            for (int mt = 0; mt < 4; mt++)
                #pragma unroll
                for (int nt = 0; nt < 8; nt++)
                    mma_any<PREC>(acc[mt][nt], af[mt], bf2[nt>>1][(nt&1)*2], bf2[nt>>1][(nt&1)*2+1]);
        }
    }

    int mW = mBase + wm*64;
    int nW = nBase + wn*64;
    #pragma unroll
    for (int mt = 0; mt < 4; mt++) {
        int r0 = mW + mt*16 + (lane >> 2);
        int r1 = r0 + 8;
        float rs0 = 1.f, rs1 = 1.f;
        if (rowdiv) { rs0 = 1.f / rowdiv[r0]; rs1 = 1.f / rowdiv[r1]; }
        float* c0 = C + (long)r0 * ldc;
        float* c1 = C + (long)r1 * ldc;
        #pragma unroll
        for (int nt = 0; nt < 8; nt++) {
            int cn = nW + nt*8 + 2*(lane & 3);
            const float* dv = acc[mt][nt];
            #pragma unroll
            for (int e = 0; e < 2; e++) {
                int col = cn + e;
                if (col < N) {
                    float b0 = 0.f;
                    if (act == 2) {
                        int seg = col >> 10;
                        const float* bp = (seg == 0) ? bias : ((seg == 1) ? bias_b : bias_c);
                        b0 = bp[col & 1023];
                    } else if (bias) {
                        b0 = bias[col];
                    }
                    float v0 = dv[e]   * rs0 + b0;
                    float v1 = dv[e+2] * rs1 + b0;
                    bool doelu = (act == 1) || (act == 2 && col < 2048);
                    if (doelu) {
                        v0 = (v0 > 0.f) ? v0 + 1.0f : expf(v0);
                        v1 = (v1 > 0.f) ? v1 + 1.0f : expf(v1);
                    }
                    c0[col] = v0;
                    c1[col] = v1;
                }
            }
        }
    }
}

// ---------------- small kernels ----------------
__global__ void gather_kernel(const int* __restrict__ ids,
                              const float* __restrict__ emb,
                              float* __restrict__ x) {
    int row = blockIdx.x;
    int id  = ids[row];
    const float4* src = (const float4*)(emb + (long)id * DMODEL);
    float4*       dst = (float4*)(x + (long)row * DMODEL);
    for (int i = threadIdx.x; i < DMODEL/4; i += blockDim.x) dst[i] = src[i];
}
__global__ void ksum_kernel(const float* __restrict__ src, int ld, long zstride,
                            float* __restrict__ ks) {
    int d = blockIdx.x * 256 + threadIdx.x;
    int b = blockIdx.y;
    const float* p = src + (long)b * zstride + d;
    float acc = 0.f;
    #pragma unroll 8
    for (int n = 0; n < NSEQ; n++) acc += p[(long)n * ld];
    ks[b * DMODEL + d] = acc + EPS_F;
}
__global__ void z_kernel(const float* __restrict__ Q, int ld,
                         const float* __restrict__ ks, float* __restrict__ z) {
    int row  = blockIdx.x * 8 + (threadIdx.x >> 5);
    int lane = threadIdx.x & 31;
    int b    = row / NSEQ;
    const float* q = Q  + (long)row * ld;
    const float* s = ks + (long)b   * DMODEL;
    float acc = 0.f;
    #pragma unroll 4
    for (int i = lane; i < DMODEL; i += 32) acc += q[i] * s[i];
    #pragma unroll
    for (int o = 16; o; o >>= 1) acc += __shfl_xor_sync(0xffffffffu, acc, o);
    if (lane == 0) z[row] = acc;
}
__global__ void pooled_kernel(const float* __restrict__ x, float* __restrict__ out) {
    int i = blockIdx.x * blockDim.x + threadIdx.x;
    if (i >= BATCH * DMODEL) return;
    int b = i / DMODEL, d = i % DMODEL;
    out[i] = x[((long)b * NSEQ + (NSEQ - 1)) * DMODEL + d];
}

// ---------------- driver ----------------
static inline long cdivl(long a, long b){ return (a + b - 1) / b; }

extern "C" void kernel_launch(void* const* d_in, const int* in_sizes, int n_in,
                              void* d_out, int out_size) {
    const int*   ids = (const int*)  d_in[0];
    const float* emb = (const float*)d_in[1];
    const float* Wq  = (const float*)d_in[2];
    const float* bq  = (const float*)d_in[3];
    const float* Wk  = (const float*)d_in[4];
    const float* bk  = (const float*)d_in[5];
    const float* Wv  = (const float*)d_in[6];
    const float* bv  = (const float*)d_in[7];
    const float* Wo  = (const float*)d_in[8];
    const float* bo  = (const float*)d_in[9];
    const float* Wh  = (const float*)d_in[10];
    const float* bh  = (const float*)d_in[11];

    float* logits = (float*)d_out;
    float* pooled = logits + (long)MTOK * VOCAB;

    float *x, *qkv, *Wbuf, *ks, *z;
    __nv_bfloat16 *xs, *qs, *kts, *vts, *wbuf, *Wsp, *wos, *whs;
    cudaGetSymbolAddress((void**)&x,    g_x);
    cudaGetSymbolAddress((void**)&qkv,  g_qkv);
    cudaGetSymbolAddress((void**)&Wbuf, g_W);
    cudaGetSymbolAddress((void**)&ks,   g_ks);
    cudaGetSymbolAddress((void**)&z,    g_z);
    cudaGetSymbolAddress((void**)&xs,   g_xs);
    cudaGetSymbolAddress((void**)&qs,   g_qs);
    cudaGetSymbolAddress((void**)&kts,  g_kts);
    cudaGetSymbolAddress((void**)&vts,  g_vts);
    cudaGetSymbolAddress((void**)&wbuf, g_wbuf);
    cudaGetSymbolAddress((void**)&Wsp,  g_Wsp);
    cudaGetSymbolAddress((void**)&wos,  g_wos);
    cudaGetSymbolAddress((void**)&whs,  g_whs);

    cudaFuncSetAttribute(hgemm_kernel<0>, cudaFuncAttributeMaxDynamicSharedMemorySize, GEMM_SMEM);
    cudaFuncSetAttribute(hgemm_kernel<1>, cudaFuncAttributeMaxDynamicSharedMemorySize, GEMM_SMEM);

    const long sTok = (long)NSEQ * DMODEL;
    const long sW   = (long)DMODEL * DMODEL;
    const long aTU  = (long)MTOK * (DMODEL/8);
    const long wTU  = (long)DMODEL * (DMODEL/8);
    const long zQKV = (long)NSEQ * QKVLD;
    const long sKts = (long)DMODEL * K3N;
    const long sWsp = (long)DMODEL * K3D;

    gather_kernel<<<MTOK, 256>>>(ids, emb, x);

    for (int l = 0; l < NLAYER; l++) {
        const float* wq = Wq + (long)l * sW;
        const float* wk = Wk + (long)l * sW;
        const float* wv = Wv + (long)l * sW;
        const float* wo = Wo + (long)l * sW;
        const float* bql = bq + (long)l * DMODEL;
        const float* bkl = bk + (long)l * DMODEL;
        const float* bvl = bv + (long)l * DMODEL;
        const float* bol = bo + (long)l * DMODEL;

        pack_a_direct<<<(unsigned)cdivl(aTU,256), 256>>>(x, MTOK, DMODEL, DMODEL, xs);
        pack_b_direct<<<(unsigned)cdivl(wTU,256), 256>>>(wq, DMODEL, DMODEL, DMODEL, wbuf, 0, 0);
        pack_b_direct<<<(unsigned)cdivl(wTU,256), 256>>>(wk, DMODEL, DMODEL, DMODEL,
            wbuf + (long)DMODEL*K3D, 0, 0);
        pack_b_direct<<<(unsigned)cdivl(wTU,256), 256>>>(wv, DMODEL, DMODEL, DMODEL,
            wbuf + (long)2*DMODEL*K3D, 0, 0);
        // fused QKV GEMM: M=4096, N=3072
        hgemm_kernel<0><<<dim3(32, 12, 1), 256, GEMM_SMEM>>>(xs, wbuf, 0, 0, K3D, 3*DMODEL,
            qkv, QKVLD, 0, bql, bkl, bvl, nullptr, 0, 2);

        {
            dim3 gT(DMODEL/32, NSEQ/64, BATCH);
            pack_trans_tiled<true ><<<gT, 256>>>(qkv + DMODEL,   QKVLD, NSEQ, kts, zQKV, sKts);
            pack_trans_tiled<false><<<gT, 256>>>(qkv + 2*DMODEL, QKVLD, NSEQ, vts, zQKV, sKts);
        }
        // W2[d,e] = sum_n K[n,d] V[n,e]
        hgemm_kernel<0><<<dim3(8, 4, BATCH), 256, GEMM_SMEM>>>(kts, vts,
            sKts, sKts, K3N, DMODEL, Wbuf, DMODEL, sW,
            nullptr, nullptr, nullptr, nullptr, 0, 0);

        ksum_kernel<<<dim3(DMODEL/256, BATCH), 256>>>(qkv + DMODEL, QKVLD, zQKV, ks);
        z_kernel<<<MTOK/8, 256>>>(qkv, QKVLD, ks, z);

        pack_a_direct<<<(unsigned)cdivl(aTU,256), 256>>>(qkv, MTOK, DMODEL, QKVLD, qs);
        pack_a_direct<<<(unsigned)cdivl(wTU,256), 256>>>(wo, DMODEL, DMODEL, DMODEL, wos);
        pack_b_direct<<<dim3((unsigned)cdivl(wTU,256), BATCH), 256>>>(Wbuf, DMODEL, DMODEL, DMODEL,
            Wsp, sW, sWsp);
        // G[i,d] = sum_e Wo[i,e] W2[d,e]
        hgemm_kernel<0><<<dim3(8, 4, BATCH), 256, GEMM_SMEM>>>(wos, Wsp,
            0, sWsp, K3D, DMODEL, Wbuf, DMODEL, sW,
            nullptr, nullptr, nullptr, nullptr, 0, 0);
        pack_b_direct<<<dim3((unsigned)cdivl(wTU,256), BATCH), 256>>>(Wbuf, DMODEL, DMODEL, DMODEL,
            vts, sW, sWsp);
        // x = (Q . G^T)/Z + bo
        hgemm_kernel<0><<<dim3(16, 4, BATCH), 256, GEMM_SMEM>>>(qs, vts,
            (long)NSEQ*K3D, sWsp, K3D, DMODEL, x, DMODEL, sTok,
            bol, nullptr, nullptr, z, NSEQ, 0);
    }

    // head: logits = x @ Wh^T + bh  (fp16 1-term)
    {
        long total = (long)NPAD_H * (DMODEL/8);
        cvt_fp16<<<(unsigned)cdivl(total,256), 256>>>(Wh, VOCAB, DMODEL, NPAD_H, (__half*)whs);
        cvt_fp16<<<(unsigned)cdivl(aTU,256), 256>>>(x, MTOK, DMODEL, MTOK, (__half*)xs);
        hgemm_kernel<1><<<dim3(32, NTILES_H, 1), 256, GEMM_SMEM>>>(xs, whs, 0, 0, DMODEL, VOCAB,
            logits, VOCAB, 0, bh, nullptr, nullptr, nullptr, 0, 0);
    }

    pooled_kernel<<<(BATCH * DMODEL + 255) / 256, 256>>>(x, pooled);
}

// round 12
// speedup vs baseline: 1.2147x; 1.2147x over previous
#include <cuda_runtime.h>
#include <cuda_bf16.h>
#include <cuda_fp16.h>
#include <math.h>
#include <stdint.h>

#define BATCH 2
#define NSEQ  2048
#define DMODEL 1024
#define NLAYER 2
#define VOCAB 50257
#define EPS_F 1e-6f
#define MTOK (BATCH*NSEQ)          // 4096
#define NTILES_H 393               // ceil(50257/128)
#define NPAD_H (NTILES_H*128)      // 50304
#define K3D (3*DMODEL)             // 3072
#define K3N (3*NSEQ)               // 6144
#define QKVLD (3*DMODEL)

// ---------------- scratch ----------------
__device__ float g_x  [MTOK*DMODEL];
__device__ float g_qkv[(long)MTOK*3*DMODEL];
__device__ float g_W  [BATCH*DMODEL*DMODEL];
__device__ float g_ks [BATCH*DMODEL];
__device__ float g_z  [MTOK];

__device__ __align__(128) __nv_bfloat16 g_xs [(long)MTOK*K3D];
__device__ __align__(128) __nv_bfloat16 g_qs [(long)MTOK*K3D];
__device__ __align__(128) __nv_bfloat16 g_kts[(long)BATCH*DMODEL*K3N];
__device__ __align__(128) __nv_bfloat16 g_vts[(long)BATCH*DMODEL*K3N];
__device__ __align__(128) __nv_bfloat16 g_wbuf[(long)3*DMODEL*K3D];  // weights; last layer: fp16 head x
__device__ __align__(128) __nv_bfloat16 g_Wsp[(long)BATCH*DMODEL*K3D];
__device__ __align__(128) __nv_bfloat16 g_wos[(long)DMODEL*K3D];
__device__ __align__(128) __nv_bfloat16 g_whs[(long)NPAD_H*DMODEL];

// ---------------- helpers ----------------
__device__ __forceinline__ uint32_t smem_u32(const void* p){
    uint32_t a;
    asm("{ .reg .u64 t; cvta.to.shared.u64 t, %1; cvt.u32.u64 %0, t; }" : "=r"(a) : "l"(p));
    return a;
}
__device__ __forceinline__ void ldsm_x4(uint32_t* r, uint32_t addr){
    asm volatile("ldmatrix.sync.aligned.m8n8.x4.shared.b16 {%0,%1,%2,%3}, [%4];"
        : "=r"(r[0]), "=r"(r[1]), "=r"(r[2]), "=r"(r[3]) : "r"(addr));
}
template<int PREC>
__device__ __forceinline__ void mma_any(float* d, const uint32_t* a, uint32_t b0, uint32_t b1){
    if (PREC == 0) {
        asm volatile("mma.sync.aligned.m16n8k16.row.col.f32.bf16.bf16.f32 "
            "{%0,%1,%2,%3}, {%4,%5,%6,%7}, {%8,%9}, {%0,%1,%2,%3};"
            : "+f"(d[0]), "+f"(d[1]), "+f"(d[2]), "+f"(d[3])
            : "r"(a[0]), "r"(a[1]), "r"(a[2]), "r"(a[3]), "r"(b0), "r"(b1));
    } else {
        asm volatile("mma.sync.aligned.m16n8k16.row.col.f32.f16.f16.f32 "
            "{%0,%1,%2,%3}, {%4,%5,%6,%7}, {%8,%9}, {%0,%1,%2,%3};"
            : "+f"(d[0]), "+f"(d[1]), "+f"(d[2]), "+f"(d[3])
            : "r"(a[0]), "r"(a[1]), "r"(a[2]), "r"(a[3]), "r"(b0), "r"(b1));
    }
}
__device__ __forceinline__ void cp16(uint32_t saddr, const void* g){
    asm volatile("cp.async.cg.shared.global.L2::128B [%0], [%1], 16;" :: "r"(saddr), "l"(g));
}
#define CP_COMMIT() asm volatile("cp.async.commit_group;" ::: "memory")
#define CP_WAIT(n)  asm volatile("cp.async.wait_group %0;" :: "n"(n) : "memory")

__device__ __forceinline__ void split8(const float* xv, uint4* hi, uint4* lo){
    __align__(16) __nv_bfloat16 h[8], l[8];
    #pragma unroll
    for (int j = 0; j < 8; j++) {
        h[j] = __float2bfloat16(xv[j]);
        l[j] = __float2bfloat16(xv[j] - __bfloat162float(h[j]));
    }
    *hi = *(const uint4*)h;
    *lo = *(const uint4*)l;
}

// ---------------- pack kernels ------------------------
// A' triple layout: group g (8 src k) = 24 bf16 at g*24: [hi|hi|lo]; B': [hi|lo|hi]
__global__ void pack_a_direct(const float* __restrict__ src, int Mr, int Kd, int lda,
                              __nv_bfloat16* __restrict__ dst) {
    int kUnits = Kd >> 3;
    long u = (long)blockIdx.x * blockDim.x + threadIdx.x;
    if (u >= (long)Mr * kUnits) return;
    int m  = (int)(u / kUnits);
    int ku = (int)(u % kUnits);
    const float4* s = (const float4*)(src + (long)m * lda + ((long)ku << 3));
    float4 a = s[0], b = s[1];
    float xv[8] = {a.x, a.y, a.z, a.w, b.x, b.y, b.z, b.w};
    uint4 hi, lo; split8(xv, &hi, &lo);
    __nv_bfloat16* base = dst + (long)m * (3*Kd) + (long)ku * 24;
    *(uint4*)(base)      = hi;
    *(uint4*)(base + 8)  = hi;
    *(uint4*)(base + 16) = lo;
}

__global__ void pack_b_direct(const float* __restrict__ src, int Nr, int Kd, int Npad,
                              __nv_bfloat16* __restrict__ dst, long sSrcZ, long sDstZ) {
    int zb = blockIdx.y;
    src += (long)zb * sSrcZ; dst += (long)zb * sDstZ;
    int kUnits = Kd >> 3;
    long u = (long)blockIdx.x * blockDim.x + threadIdx.x;
    if (u >= (long)Npad * kUnits) return;
    int n  = (int)(u / kUnits);
    int ku = (int)(u % kUnits);
    float xv[8] = {0.f,0.f,0.f,0.f,0.f,0.f,0.f,0.f};
    if (n < Nr) {
        const float4* s = (const float4*)(src + (long)n * Kd + ((long)ku << 3));
        float4 a = s[0], b = s[1];
        xv[0]=a.x; xv[1]=a.y; xv[2]=a.z; xv[3]=a.w; xv[4]=b.x; xv[5]=b.y; xv[6]=b.z; xv[7]=b.w;
    }
    uint4 hi, lo; split8(xv, &hi, &lo);
    __nv_bfloat16* base = dst + (long)n * (3*Kd) + (long)ku * 24;
    *(uint4*)(base)      = hi;
    *(uint4*)(base + 8)  = lo;
    *(uint4*)(base + 16) = hi;
}

// fused 3-way weight pack (Wq/Wk/Wv), 1024x1024 each, B' layout
__global__ void pack_b3(const float* __restrict__ w0, const float* __restrict__ w1,
                        const float* __restrict__ w2, __nv_bfloat16* __restrict__ dst) {
    const float* src = (blockIdx.y == 0) ? w0 : ((blockIdx.y == 1) ? w1 : w2);
    dst += (long)blockIdx.y * DMODEL * K3D;
    long u = (long)blockIdx.x * blockDim.x + threadIdx.x;
    if (u >= (long)DMODEL * 128) return;
    int n  = (int)(u >> 7);
    int ku = (int)(u & 127);
    const float4* s = (const float4*)(src + (long)n * DMODEL + ((long)ku << 3));
    float4 a = s[0], b = s[1];
    float xv[8] = {a.x, a.y, a.z, a.w, b.x, b.y, b.z, b.w};
    uint4 hi, lo; split8(xv, &hi, &lo);
    __nv_bfloat16* base = dst + (long)n * K3D + (long)ku * 24;
    *(uint4*)(base)      = hi;
    *(uint4*)(base + 8)  = lo;
    *(uint4*)(base + 16) = hi;
}

// fast fp32->fp16 convert (16 elem/thread), Kd fixed = 1024, rows padded to Npad
// FIXED: use a contiguous local array (previous version read across separate
// float4 locals via pointer arithmetic — UB, produced garbage head weights).
__global__ void cvt_fp16_fast(const float* __restrict__ src, int Nr, int Npad,
                              __half* __restrict__ dst) {
    long u = (long)blockIdx.x * blockDim.x + threadIdx.x;
    if (u >= (long)Npad * 64) return;
    int n  = (int)(u >> 6);
    int kb = (int)(u & 63);
    __align__(16) float f[16];
    #pragma unroll
    for (int j = 0; j < 16; j++) f[j] = 0.f;
    if (n < Nr) {
        const float4* s = (const float4*)(src + (long)n * 1024 + (long)kb * 16);
        float4* fd = (float4*)f;
        fd[0] = s[0]; fd[1] = s[1]; fd[2] = s[2]; fd[3] = s[3];
    }
    __align__(16) __half h[16];
    #pragma unroll
    for (int j = 0; j < 16; j++) h[j] = __float2half(f[j]);
    uint4* d = (uint4*)(dst + (long)n * 1024 + (long)kb * 16);
    d[0] = ((uint4*)h)[0];
    d[1] = ((uint4*)h)[1];
}

// SMEM-tiled transpose packs
template<bool ISA>
__global__ void pack_trans_tiled(const float* __restrict__ src, int ld, int Kd,
                                 __nv_bfloat16* __restrict__ dst, long sSrcZ, long sDstZ) {
    __shared__ float t[64][33];
    int zb = blockIdx.z;
    src += (long)zb * sSrcZ; dst += (long)zb * sDstZ;
    int r0 = blockIdx.x * 32, k0 = blockIdx.y * 64;
    int tid = threadIdx.x;
    #pragma unroll
    for (int i = 0; i < 8; i++) {
        int idx = tid + i * 256;
        int k = idx >> 5, r = idx & 31;
        t[k][r] = src[(long)(k0 + k) * ld + r0 + r];
    }
    __syncthreads();
    int r = tid >> 3, kg = tid & 7;
    float xv[8];
    #pragma unroll
    for (int j = 0; j < 8; j++) xv[j] = t[kg*8 + j][r];
    uint4 hi, lo; split8(xv, &hi, &lo);
    __nv_bfloat16* base = dst + (long)(r0 + r) * (3*Kd) + (long)((k0 >> 3) + kg) * 24;
    if (ISA) {
        *(uint4*)(base)      = hi;
        *(uint4*)(base + 8)  = hi;
        *(uint4*)(base + 16) = lo;
    } else {
        *(uint4*)(base)      = hi;
        *(uint4*)(base + 8)  = lo;
        *(uint4*)(base + 16) = hi;
    }
}

// ---------------- HMMA GEMM (128x128, BK=64, 3 stages, 2 CTA/SM) ----
// act: 0 = linear, 1 = elu+1, 2 = QKV fused.
// Cbf (optional): packed A'-triple output of first npk columns (row len 3*npk).
// Chf (optional): fp16 row-major output of first npk columns.
#define STAGES 3
#define STAGE_BYTES 32768
#define GEMM_SMEM (STAGES*STAGE_BYTES)

template<int PREC>
__global__ __launch_bounds__(256, 2)
void hgemm_kernel(const __nv_bfloat16* __restrict__ A,
                  const __nv_bfloat16* __restrict__ B,
                  long sA, long sB,
                  int K3, int N,
                  float* __restrict__ C, int ldc, long sC,
                  const float* __restrict__ bias,
                  const float* __restrict__ bias_b,
                  const float* __restrict__ bias_c,
                  const float* __restrict__ rowdiv, long sR,
                  int act,
                  __nv_bfloat16* __restrict__ Cbf, long sCbf,
                  __half* __restrict__ Chf, long sChf,
                  int npk)
{
    extern __shared__ char smem[];
    uint32_t sbase = smem_u32(smem);
    int tid = threadIdx.x;
    int lane = tid & 31, wid = tid >> 5;
    int wm = wid >> 2, wn = wid & 3;
    int mBase = blockIdx.x * 128;
    int nBase = blockIdx.y * 128;
    int zb = blockIdx.z;
    A += (long)zb * sA; B += (long)zb * sB; C += (long)zb * sC;
    if (rowdiv) rowdiv += (long)zb * sR;
    if (Cbf) Cbf += (long)zb * sCbf;
    if (Chf) Chf += (long)zb * sChf;

    const char* aG = (const char*)(A + (long)mBase * K3);
    const char* bG = (const char*)(B + (long)nBase * K3);
    long ldg = (long)K3 * 2;

    int lr = tid >> 3;
    int la = tid & 7;

    float acc[4][4][4];
    #pragma unroll
    for (int i = 0; i < 4; i++)
        #pragma unroll
        for (int j = 0; j < 4; j++)
            #pragma unroll
            for (int e = 0; e < 4; e++) acc[i][j][e] = 0.f;

    int nK = K3 >> 6;

    #pragma unroll
    for (int s = 0; s < STAGES-1; s++) {
        uint32_t aS = sbase + s*STAGE_BYTES;
        uint32_t bS = aS + 16384;
        const char* ag = aG + (long)s*128;
        const char* bg = bG + (long)s*128;
        #pragma unroll
        for (int p = 0; p < 4; p++) {
            int r = lr + p*32;
            uint32_t so = (uint32_t)r*128 + 16u*(uint32_t)(la ^ (r & 7));
            cp16(aS + so, ag + (long)r*ldg + la*16);
            cp16(bS + so, bg + (long)r*ldg + la*16);
        }
        CP_COMMIT();
    }

    for (int i = 0; i < nK; i++) {
        CP_WAIT(STAGES-2);
        __syncthreads();
        int nc = i + STAGES - 1;
        if (nc < nK) {
            int s = nc % STAGES;
            uint32_t aS = sbase + s*STAGE_BYTES;
            uint32_t bS = aS + 16384;
            const char* ag = aG + (long)nc*128;
            const char* bg = bG + (long)nc*128;
            #pragma unroll
            for (int p = 0; p < 4; p++) {
                int r = lr + p*32;
                uint32_t so = (uint32_t)r*128 + 16u*(uint32_t)(la ^ (r & 7));
                cp16(aS + so, ag + (long)r*ldg + la*16);
                cp16(bS + so, bg + (long)r*ldg + la*16);
            }
        }
        CP_COMMIT();

        int cs = i % STAGES;
        uint32_t aS = sbase + cs*STAGE_BYTES;
        uint32_t bS = aS + 16384;
        #pragma unroll
        for (int kt = 0; kt < 4; kt++) {
            uint32_t af[4][4];
            #pragma unroll
            for (int mt = 0; mt < 4; mt++) {
                int row = wm*64 + mt*16 + (lane & 15);
                int a = kt*2 + (lane >> 4);
                ldsm_x4(af[mt], aS + (uint32_t)row*128 + 16u*(uint32_t)(a ^ (row & 7)));
            }
            uint32_t bf2[2][4];
            #pragma unroll
            for (int np = 0; np < 2; np++) {
                int row = wn*32 + np*16 + ((lane >> 4) & 1)*8 + (lane & 7);
                int a = kt*2 + ((lane >> 3) & 1);
                ldsm_x4(bf2[np], bS + (uint32_t)row*128 + 16u*(uint32_t)(a ^ (row & 7)));
            }
            #pragma unroll
            for (int mt = 0; mt < 4; mt++)
                #pragma unroll
                for (int nt = 0; nt < 4; nt++)
                    mma_any<PREC>(acc[mt][nt], af[mt], bf2[nt>>1][(nt&1)*2], bf2[nt>>1][(nt&1)*2+1]);
        }
    }

    int mW = mBase + wm*64;
    int nW = nBase + wn*32;
    #pragma unroll
    for (int mt = 0; mt < 4; mt++) {
        int r0 = mW + mt*16 + (lane >> 2);
        int r1 = r0 + 8;
        float rs0 = 1.f, rs1 = 1.f;
        if (rowdiv) { rs0 = 1.f / rowdiv[r0]; rs1 = 1.f / rowdiv[r1]; }
        float* c0 = C + (long)r0 * ldc;
        float* c1 = C + (long)r1 * ldc;
        #pragma unroll
        for (int nt = 0; nt < 4; nt++) {
            int cn = nW + nt*8 + 2*(lane & 3);
            const float* dv = acc[mt][nt];
            float w0[2], w1[2];
            #pragma unroll
            for (int e = 0; e < 2; e++) {
                int col = cn + e;
                w0[e] = 0.f; w1[e] = 0.f;
                if (col < N) {
                    float b0 = 0.f;
                    if (act == 2) {
                        int seg = col >> 10;
                        const float* bp = (seg == 0) ? bias : ((seg == 1) ? bias_b : bias_c);
                        b0 = bp[col & 1023];
                    } else if (bias) {
                        b0 = bias[col];
                    }
                    float v0 = dv[e]   * rs0 + b0;
                    float v1 = dv[e+2] * rs1 + b0;
                    bool doelu = (act == 1) || (act == 2 && col < 2048);
                    if (doelu) {
                        v0 = (v0 > 0.f) ? v0 + 1.0f : expf(v0);
                        v1 = (v1 > 0.f) ? v1 + 1.0f : expf(v1);
                    }
                    c0[col] = v0;
                    c1[col] = v1;
                    w0[e] = v0; w1[e] = v1;
                }
            }
            if (Cbf && cn < npk) {
                long g = cn >> 3; int off = cn & 7;
                __align__(4) __nv_bfloat16 t2[2];
                __nv_bfloat16 hA = __float2bfloat16(w0[0]);
                __nv_bfloat16 hB = __float2bfloat16(w0[1]);
                __nv_bfloat16 lA = __float2bfloat16(w0[0] - __bfloat162float(hA));
                __nv_bfloat16 lB = __float2bfloat16(w0[1] - __bfloat162float(hB));
                __nv_bfloat16* p0 = Cbf + (long)r0 * (3*npk) + g*24 + off;
                t2[0] = hA; t2[1] = hB; uint32_t hi0 = *(uint32_t*)t2;
                t2[0] = lA; t2[1] = lB; uint32_t lo0 = *(uint32_t*)t2;
                *(uint32_t*)p0        = hi0;
                *(uint32_t*)(p0 + 8)  = hi0;
                *(uint32_t*)(p0 + 16) = lo0;
                hA = __float2bfloat16(w1[0]);
                hB = __float2bfloat16(w1[1]);
                lA = __float2bfloat16(w1[0] - __bfloat162float(hA));
                lB = __float2bfloat16(w1[1] - __bfloat162float(hB));
                __nv_bfloat16* p1 = Cbf + (long)r1 * (3*npk) + g*24 + off;
                t2[0] = hA; t2[1] = hB; uint32_t hi1 = *(uint32_t*)t2;
                t2[0] = lA; t2[1] = lB; uint32_t lo1 = *(uint32_t*)t2;
                *(uint32_t*)p1        = hi1;
                *(uint32_t*)(p1 + 8)  = hi1;
                *(uint32_t*)(p1 + 16) = lo1;
            }
            if (Chf && cn < npk) {
                __half2 h0 = __floats2half2_rn(w0[0], w0[1]);
                __half2 h1 = __floats2half2_rn(w1[0], w1[1]);
                *(uint32_t*)(Chf + (long)r0 * npk + cn) = *(uint32_t*)&h0;
                *(uint32_t*)(Chf + (long)r1 * npk + cn) = *(uint32_t*)&h1;
            }
        }
    }
}

// ---------------- small kernels ----------------
__global__ void gather_pack(const int* __restrict__ ids,
                            const float* __restrict__ emb,
                            float* __restrict__ x,
                            __nv_bfloat16* __restrict__ xs) {
    int row = blockIdx.x;
    int id  = ids[row];
    int t   = threadIdx.x;       // 0..127
    const float4* src = (const float4*)(emb + (long)id * DMODEL);
    float4* dstx = (float4*)(x + (long)row * DMODEL);
    float4 a = src[2*t], b = src[2*t + 1];
    dstx[2*t] = a; dstx[2*t + 1] = b;
    float xv[8] = {a.x, a.y, a.z, a.w, b.x, b.y, b.z, b.w};
    uint4 hi, lo; split8(xv, &hi, &lo);
    __nv_bfloat16* base = xs + (long)row * K3D + (long)t * 24;
    *(uint4*)(base)      = hi;
    *(uint4*)(base + 8)  = hi;
    *(uint4*)(base + 16) = lo;
}
__global__ void ksum_kernel(const float* __restrict__ src, int ld, long zstride,
                            float* __restrict__ ks) {
    int d = blockIdx.x * 256 + threadIdx.x;
    int b = blockIdx.y;
    const float* p = src + (long)b * zstride + d;
    float acc = 0.f;
    #pragma unroll 8
    for (int n = 0; n < NSEQ; n++) acc += p[(long)n * ld];
    ks[b * DMODEL + d] = acc + EPS_F;
}
__global__ void z_kernel(const float* __restrict__ Q, int ld,
                         const float* __restrict__ ks, float* __restrict__ z) {
    int row  = blockIdx.x * 8 + (threadIdx.x >> 5);
    int lane = threadIdx.x & 31;
    int b    = row / NSEQ;
    const float* q = Q  + (long)row * ld;
    const float* s = ks + (long)b   * DMODEL;
    float acc = 0.f;
    #pragma unroll 4
    for (int i = lane; i < DMODEL; i += 32) acc += q[i] * s[i];
    #pragma unroll
    for (int o = 16; o; o >>= 1) acc += __shfl_xor_sync(0xffffffffu, acc, o);
    if (lane == 0) z[row] = acc;
}
__global__ void pooled_kernel(const float* __restrict__ x, float* __restrict__ out) {
    int i = blockIdx.x * blockDim.x + threadIdx.x;
    if (i >= BATCH * DMODEL) return;
    int b = i / DMODEL, d = i % DMODEL;
    out[i] = x[((long)b * NSEQ + (NSEQ - 1)) * DMODEL + d];
}

// ---------------- driver ----------------
static inline long cdivl(long a, long b){ return (a + b - 1) / b; }

extern "C" void kernel_launch(void* const* d_in, const int* in_sizes, int n_in,
                              void* d_out, int out_size) {
    const int*   ids = (const int*)  d_in[0];
    const float* emb = (const float*)d_in[1];
    const float* Wq  = (const float*)d_in[2];
    const float* bq  = (const float*)d_in[3];
    const float* Wk  = (const float*)d_in[4];
    const float* bk  = (const float*)d_in[5];
    const float* Wv  = (const float*)d_in[6];
    const float* bv  = (const float*)d_in[7];
    const float* Wo  = (const float*)d_in[8];
    const float* bo  = (const float*)d_in[9];
    const float* Wh  = (const float*)d_in[10];
    const float* bh  = (const float*)d_in[11];

    float* logits = (float*)d_out;
    float* pooled = logits + (long)MTOK * VOCAB;

    float *x, *qkv, *Wbuf, *ks, *z;
    __nv_bfloat16 *xs, *qs, *kts, *vts, *wbuf, *Wsp, *wos, *whs;
    cudaGetSymbolAddress((void**)&x,    g_x);
    cudaGetSymbolAddress((void**)&qkv,  g_qkv);
    cudaGetSymbolAddress((void**)&Wbuf, g_W);
    cudaGetSymbolAddress((void**)&ks,   g_ks);
    cudaGetSymbolAddress((void**)&z,    g_z);
    cudaGetSymbolAddress((void**)&xs,   g_xs);
    cudaGetSymbolAddress((void**)&qs,   g_qs);
    cudaGetSymbolAddress((void**)&kts,  g_kts);
    cudaGetSymbolAddress((void**)&vts,  g_vts);
    cudaGetSymbolAddress((void**)&wbuf, g_wbuf);
    cudaGetSymbolAddress((void**)&Wsp,  g_Wsp);
    cudaGetSymbolAddress((void**)&wos,  g_wos);
    cudaGetSymbolAddress((void**)&whs,  g_whs);

    cudaFuncSetAttribute(hgemm_kernel<0>, cudaFuncAttributeMaxDynamicSharedMemorySize, GEMM_SMEM);
    cudaFuncSetAttribute(hgemm_kernel<1>, cudaFuncAttributeMaxDynamicSharedMemorySize, GEMM_SMEM);

    const long sTok = (long)NSEQ * DMODEL;
    const long sW   = (long)DMODEL * DMODEL;
    const long wTU  = (long)DMODEL * (DMODEL/8);
    const long zQKV = (long)NSEQ * QKVLD;
    const long sKts = (long)DMODEL * K3N;
    const long sWsp = (long)DMODEL * K3D;

    gather_pack<<<MTOK, 128>>>(ids, emb, x, xs);

    for (int l = 0; l < NLAYER; l++) {
        const float* wq = Wq + (long)l * sW;
        const float* wk = Wk + (long)l * sW;
        const float* wv = Wv + (long)l * sW;
        const float* wo = Wo + (long)l * sW;
        const float* bql = bq + (long)l * DMODEL;
        const float* bkl = bk + (long)l * DMODEL;
        const float* bvl = bv + (long)l * DMODEL;
        const float* bol = bo + (long)l * DMODEL;
        bool last = (l == NLAYER - 1);

        pack_b3<<<dim3(512, 3), 256>>>(wq, wk, wv, wbuf);

        // fused QKV GEMM; epilogue also emits packed Q panel (qs)
        hgemm_kernel<0><<<dim3(32, 24, 1), 256, GEMM_SMEM>>>(xs, wbuf, 0, 0, K3D, 3*DMODEL,
            qkv, QKVLD, 0, bql, bkl, bvl, nullptr, 0, 2,
            qs, 0, nullptr, 0, DMODEL);

        {
            dim3 gT(DMODEL/32, NSEQ/64, BATCH);
            pack_trans_tiled<true ><<<gT, 256>>>(qkv + DMODEL,   QKVLD, NSEQ, kts, zQKV, sKts);
            pack_trans_tiled<false><<<gT, 256>>>(qkv + 2*DMODEL, QKVLD, NSEQ, vts, zQKV, sKts);
        }
        // W2[d,e] = sum_n K[n,d] V[n,e]
        hgemm_kernel<0><<<dim3(8, 8, BATCH), 256, GEMM_SMEM>>>(kts, vts,
            sKts, sKts, K3N, DMODEL, Wbuf, DMODEL, sW,
            nullptr, nullptr, nullptr, nullptr, 0, 0,
            nullptr, 0, nullptr, 0, 0);

        ksum_kernel<<<dim3(DMODEL/256, BATCH), 256>>>(qkv + DMODEL, QKVLD, zQKV, ks);
        z_kernel<<<MTOK/8, 256>>>(qkv, QKVLD, ks, z);

        pack_a_direct<<<(unsigned)cdivl(wTU,256), 256>>>(wo, DMODEL, DMODEL, DMODEL, wos);
        pack_b_direct<<<dim3((unsigned)cdivl(wTU,256), BATCH), 256>>>(Wbuf, DMODEL, DMODEL, DMODEL,
            Wsp, sW, sWsp);
        // G[i,d] = sum_e Wo[i,e] W2[d,e]
        hgemm_kernel<0><<<dim3(8, 8, BATCH), 256, GEMM_SMEM>>>(wos, Wsp,
            0, sWsp, K3D, DMODEL, Wbuf, DMODEL, sW,
            nullptr, nullptr, nullptr, nullptr, 0, 0,
            nullptr, 0, nullptr, 0, 0);
        pack_b_direct<<<dim3((unsigned)cdivl(wTU,256), BATCH), 256>>>(Wbuf, DMODEL, DMODEL, DMODEL,
            vts, sW, sWsp);
        // x = (Q . G^T)/Z + bo ; epilogue emits next-layer xs and (last) fp16 head x
        hgemm_kernel<0><<<dim3(16, 8, BATCH), 256, GEMM_SMEM>>>(qs, vts,
            (long)NSEQ*K3D, sWsp, K3D, DMODEL, x, DMODEL, sTok,
            bol, nullptr, nullptr, z, NSEQ, 0,
            xs, (long)NSEQ*K3D, last ? (__half*)wbuf : nullptr, (long)NSEQ*DMODEL, DMODEL);
    }

    // head: logits = fp16(x) @ fp16(Wh)^T + bh
    {
        long total = (long)NPAD_H * 64;
        cvt_fp16_fast<<<(unsigned)cdivl(total,256), 256>>>(Wh, VOCAB, NPAD_H, (__half*)whs);
        hgemm_kernel<1><<<dim3(32, NTILES_H, 1), 256, GEMM_SMEM>>>(wbuf, whs, 0, 0, DMODEL, VOCAB,
            logits, VOCAB, 0, bh, nullptr, nullptr, nullptr, 0, 0,
            nullptr, 0, nullptr, 0, 0);
    }

    pooled_kernel<<<(BATCH * DMODEL + 255) / 256, 256>>>(x, pooled);
}

// round 14
// speedup vs baseline: 1.2172x; 1.0021x over previous
#include <cuda_runtime.h>
#include <cuda_bf16.h>
#include <cuda_fp16.h>
#include <math.h>
#include <stdint.h>

#define BATCH 2
#define NSEQ  2048
#define DMODEL 1024
#define NLAYER 2
#define VOCAB 50257
#define EPS_F 1e-6f
#define MTOK (BATCH*NSEQ)          // 4096
#define NTILES_H 393               // ceil(50257/128)
#define NPAD_H (NTILES_H*128)      // 50304
#define K3D (3*DMODEL)             // 3072
#define K3N (3*NSEQ)               // 6144
#define QKVLD (3*DMODEL)
#define MNW ((long)DMODEL*DMODEL)  // 1M elements

// ---------------- scratch ----------------
__device__ float g_x  [MTOK*DMODEL];
__device__ float g_qkv[(long)MTOK*3*DMODEL];
__device__ float g_part[(long)BATCH*4*DMODEL*DMODEL];   // split-K partials (33.5MB)
__device__ float g_ks [BATCH*DMODEL];
__device__ float g_z  [MTOK];

__device__ __align__(128) __nv_bfloat16 g_xs [(long)MTOK*K3D];
__device__ __align__(128) __nv_bfloat16 g_qs [(long)MTOK*K3D];
__device__ __align__(128) __nv_bfloat16 g_kts[(long)BATCH*DMODEL*K3N];
__device__ __align__(128) __nv_bfloat16 g_vts[(long)BATCH*DMODEL*K3N];
__device__ __align__(128) __nv_bfloat16 g_wbuf[(long)3*DMODEL*K3D];  // weights; last layer: fp16 head x
__device__ __align__(128) __nv_bfloat16 g_Wsp[(long)BATCH*DMODEL*K3D];
__device__ __align__(128) __nv_bfloat16 g_wos[(long)DMODEL*K3D];
__device__ __align__(128) __nv_bfloat16 g_whs[(long)NPAD_H*DMODEL];

// ---------------- helpers ----------------
__device__ __forceinline__ uint32_t smem_u32(const void* p){
    uint32_t a;
    asm("{ .reg .u64 t; cvta.to.shared.u64 t, %1; cvt.u32.u64 %0, t; }" : "=r"(a) : "l"(p));
    return a;
}
__device__ __forceinline__ void ldsm_x4(uint32_t* r, uint32_t addr){
    asm volatile("ldmatrix.sync.aligned.m8n8.x4.shared.b16 {%0,%1,%2,%3}, [%4];"
        : "=r"(r[0]), "=r"(r[1]), "=r"(r[2]), "=r"(r[3]) : "r"(addr));
}
template<int PREC>
__device__ __forceinline__ void mma_any(float* d, const uint32_t* a, uint32_t b0, uint32_t b1){
    if (PREC == 0) {
        asm volatile("mma.sync.aligned.m16n8k16.row.col.f32.bf16.bf16.f32 "
            "{%0,%1,%2,%3}, {%4,%5,%6,%7}, {%8,%9}, {%0,%1,%2,%3};"
            : "+f"(d[0]), "+f"(d[1]), "+f"(d[2]), "+f"(d[3])
            : "r"(a[0]), "r"(a[1]), "r"(a[2]), "r"(a[3]), "r"(b0), "r"(b1));
    } else {
        asm volatile("mma.sync.aligned.m16n8k16.row.col.f32.f16.f16.f32 "
            "{%0,%1,%2,%3}, {%4,%5,%6,%7}, {%8,%9}, {%0,%1,%2,%3};"
            : "+f"(d[0]), "+f"(d[1]), "+f"(d[2]), "+f"(d[3])
            : "r"(a[0]), "r"(a[1]), "r"(a[2]), "r"(a[3]), "r"(b0), "r"(b1));
    }
}
__device__ __forceinline__ void cp16(uint32_t saddr, const void* g){
    asm volatile("cp.async.cg.shared.global.L2::128B [%0], [%1], 16;" :: "r"(saddr), "l"(g));
}
#define CP_COMMIT() asm volatile("cp.async.commit_group;" ::: "memory")
#define CP_WAIT(n)  asm volatile("cp.async.wait_group %0;" :: "n"(n) : "memory")

__device__ __forceinline__ void split8(const float* xv, uint4* hi, uint4* lo){
    __align__(16) __nv_bfloat16 h[8], l[8];
    #pragma unroll
    for (int j = 0; j < 8; j++) {
        h[j] = __float2bfloat16(xv[j]);
        l[j] = __float2bfloat16(xv[j] - __bfloat162float(h[j]));
    }
    *hi = *(const uint4*)h;
    *lo = *(const uint4*)l;
}

// ---------------- pack kernels ------------------------
// A' triple layout: group g (8 src k) = 24 bf16 at g*24: [hi|hi|lo]; B': [hi|lo|hi]
__global__ void pack_a_direct(const float* __restrict__ src, int Mr, int Kd, int lda,
                              __nv_bfloat16* __restrict__ dst) {
    int kUnits = Kd >> 3;
    long u = (long)blockIdx.x * blockDim.x + threadIdx.x;
    if (u >= (long)Mr * kUnits) return;
    int m  = (int)(u / kUnits);
    int ku = (int)(u % kUnits);
    const float4* s = (const float4*)(src + (long)m * lda + ((long)ku << 3));
    float4 a = s[0], b = s[1];
    float xv[8] = {a.x, a.y, a.z, a.w, b.x, b.y, b.z, b.w};
    uint4 hi, lo; split8(xv, &hi, &lo);
    __nv_bfloat16* base = dst + (long)m * (3*Kd) + (long)ku * 24;
    *(uint4*)(base)      = hi;
    *(uint4*)(base + 8)  = hi;
    *(uint4*)(base + 16) = lo;
}

// sum nsplit fp32 partial slices [1024,1024] then pack as B' [hi|lo|hi]
__global__ void pack_b_sum(const float* __restrict__ part, int nsplit,
                           __nv_bfloat16* __restrict__ dst, long sDstZ) {
    int zb = blockIdx.y;
    part += (long)zb * nsplit * MNW;
    dst  += (long)zb * sDstZ;
    long u = (long)blockIdx.x * blockDim.x + threadIdx.x;
    if (u >= (long)DMODEL * 128) return;
    int n  = (int)(u >> 7);
    int ku = (int)(u & 127);
    float xv[8] = {0.f,0.f,0.f,0.f,0.f,0.f,0.f,0.f};
    for (int sp = 0; sp < nsplit; sp++) {
        const float4* s = (const float4*)(part + (long)sp * MNW + (long)n * DMODEL + ((long)ku << 3));
        float4 a = s[0], b = s[1];
        xv[0]+=a.x; xv[1]+=a.y; xv[2]+=a.z; xv[3]+=a.w;
        xv[4]+=b.x; xv[5]+=b.y; xv[6]+=b.z; xv[7]+=b.w;
    }
    uint4 hi, lo; split8(xv, &hi, &lo);
    __nv_bfloat16* base = dst + (long)n * K3D + (long)ku * 24;
    *(uint4*)(base)      = hi;
    *(uint4*)(base + 8)  = lo;
    *(uint4*)(base + 16) = hi;
}

// fused 3-way weight pack (Wq/Wk/Wv), 1024x1024 each, B' layout
__global__ void pack_b3(const float* __restrict__ w0, const float* __restrict__ w1,
                        const float* __restrict__ w2, __nv_bfloat16* __restrict__ dst) {
    const float* src = (blockIdx.y == 0) ? w0 : ((blockIdx.y == 1) ? w1 : w2);
    dst += (long)blockIdx.y * DMODEL * K3D;
    long u = (long)blockIdx.x * blockDim.x + threadIdx.x;
    if (u >= (long)DMODEL * 128) return;
    int n  = (int)(u >> 7);
    int ku = (int)(u & 127);
    const float4* s = (const float4*)(src + (long)n * DMODEL + ((long)ku << 3));
    float4 a = s[0], b = s[1];
    float xv[8] = {a.x, a.y, a.z, a.w, b.x, b.y, b.z, b.w};
    uint4 hi, lo; split8(xv, &hi, &lo);
    __nv_bfloat16* base = dst + (long)n * K3D + (long)ku * 24;
    *(uint4*)(base)      = hi;
    *(uint4*)(base + 8)  = lo;
    *(uint4*)(base + 16) = hi;
}

// fast fp32->fp16 convert (16 elem/thread), Kd fixed = 1024, rows padded to Npad
__global__ void cvt_fp16_fast(const float* __restrict__ src, int Nr, int Npad,
                              __half* __restrict__ dst) {
    long u = (long)blockIdx.x * blockDim.x + threadIdx.x;
    if (u >= (long)Npad * 64) return;
    int n  = (int)(u >> 6);
    int kb = (int)(u & 63);
    __align__(16) float f[16];
    #pragma unroll
    for (int j = 0; j < 16; j++) f[j] = 0.f;
    if (n < Nr) {
        const float4* s = (const float4*)(src + (long)n * 1024 + (long)kb * 16);
        float4* fd = (float4*)f;
        fd[0] = s[0]; fd[1] = s[1]; fd[2] = s[2]; fd[3] = s[3];
    }
    __align__(16) __half h[16];
    #pragma unroll
    for (int j = 0; j < 16; j++) h[j] = __float2half(f[j]);
    uint4* d = (uint4*)(dst + (long)n * 1024 + (long)kb * 16);
    d[0] = ((uint4*)h)[0];
    d[1] = ((uint4*)h)[1];
}

// SMEM-tiled transpose packs
template<bool ISA>
__global__ void pack_trans_tiled(const float* __restrict__ src, int ld, int Kd,
                                 __nv_bfloat16* __restrict__ dst, long sSrcZ, long sDstZ) {
    __shared__ float t[64][33];
    int zb = blockIdx.z;
    src += (long)zb * sSrcZ; dst += (long)zb * sDstZ;
    int r0 = blockIdx.x * 32, k0 = blockIdx.y * 64;
    int tid = threadIdx.x;
    #pragma unroll
    for (int i = 0; i < 8; i++) {
        int idx = tid + i * 256;
        int k = idx >> 5, r = idx & 31;
        t[k][r] = src[(long)(k0 + k) * ld + r0 + r];
    }
    __syncthreads();
    int r = tid >> 3, kg = tid & 7;
    float xv[8];
    #pragma unroll
    for (int j = 0; j < 8; j++) xv[j] = t[kg*8 + j][r];
    uint4 hi, lo; split8(xv, &hi, &lo);
    __nv_bfloat16* base = dst + (long)(r0 + r) * (3*Kd) + (long)((k0 >> 3) + kg) * 24;
    if (ISA) {
        *(uint4*)(base)      = hi;
        *(uint4*)(base + 8)  = hi;
        *(uint4*)(base + 16) = lo;
    } else {
        *(uint4*)(base)      = hi;
        *(uint4*)(base + 8)  = lo;
        *(uint4*)(base + 16) = hi;
    }
}

// ---------------- HMMA GEMM (128x128, BK=64, 3 stages, 2 CTA/SM) ----
// Kfull = row stride (elements), Klen = K covered by this launch slice.
// nsplit>1: blockIdx.z = zb*nsplit + sp; slice sp covers K cols [sp*Klen, ...);
//           C indexed by blockIdx.z (partial buffer), no bias/act expected.
#define STAGES 3
#define STAGE_BYTES 32768
#define GEMM_SMEM (STAGES*STAGE_BYTES)

template<int PREC>
__global__ __launch_bounds__(256, 2)
void hgemm_kernel(const __nv_bfloat16* __restrict__ A,
                  const __nv_bfloat16* __restrict__ B,
                  long sA, long sB,
                  int Kfull, int Klen, int N,
                  float* __restrict__ C, int ldc, long sC,
                  const float* __restrict__ bias,
                  const float* __restrict__ bias_b,
                  const float* __restrict__ bias_c,
                  const float* __restrict__ rowdiv, long sR,
                  int act,
                  __nv_bfloat16* __restrict__ Cbf, long sCbf,
                  __half* __restrict__ Chf, long sChf,
                  int npk, int nsplit)
{
    extern __shared__ char smem[];
    uint32_t sbase = smem_u32(smem);
    int tid = threadIdx.x;
    int lane = tid & 31, wid = tid >> 5;
    int wm = wid >> 2, wn = wid & 3;
    int mBase = blockIdx.x * 128;
    int nBase = blockIdx.y * 128;
    int zAll = blockIdx.z;
    int sp = 0, zb = zAll;
    if (nsplit > 1) { sp = zAll % nsplit; zb = zAll / nsplit; }
    A += (long)zb * sA + (long)sp * Klen;
    B += (long)zb * sB + (long)sp * Klen;
    C += (long)zAll * sC;
    if (rowdiv) rowdiv += (long)zb * sR;
    if (Cbf) Cbf += (long)zb * sCbf;
    if (Chf) Chf += (long)zb * sChf;

    const char* aG = (const char*)(A + (long)mBase * Kfull);
    const char* bG = (const char*)(B + (long)nBase * Kfull);
    long ldg = (long)Kfull * 2;

    int lr = tid >> 3;
    int la = tid & 7;

    float acc[4][4][4];
    #pragma unroll
    for (int i = 0; i < 4; i++)
        #pragma unroll
        for (int j = 0; j < 4; j++)
            #pragma unroll
            for (int e = 0; e < 4; e++) acc[i][j][e] = 0.f;

    int nK = Klen >> 6;

    #pragma unroll
    for (int s = 0; s < STAGES-1; s++) {
        uint32_t aS = sbase + s*STAGE_BYTES;
        uint32_t bS = aS + 16384;
        const char* ag = aG + (long)s*128;
        const char* bg = bG + (long)s*128;
        #pragma unroll
        for (int p = 0; p < 4; p++) {
            int r = lr + p*32;
            uint32_t so = (uint32_t)r*128 + 16u*(uint32_t)(la ^ (r & 7));
            cp16(aS + so, ag + (long)r*ldg + la*16);
            cp16(bS + so, bg + (long)r*ldg + la*16);
        }
        CP_COMMIT();
    }

    for (int i = 0; i < nK; i++) {
        CP_WAIT(STAGES-2);
        __syncthreads();
        int nc = i + STAGES - 1;
        if (nc < nK) {
            int s = nc % STAGES;
            uint32_t aS = sbase + s*STAGE_BYTES;
            uint32_t bS = aS + 16384;
            const char* ag = aG + (long)nc*128;
            const char* bg = bG + (long)nc*128;
            #pragma unroll
            for (int p = 0; p < 4; p++) {
                int r = lr + p*32;
                uint32_t so = (uint32_t)r*128 + 16u*(uint32_t)(la ^ (r & 7));
                cp16(aS + so, ag + (long)r*ldg + la*16);
                cp16(bS + so, bg + (long)r*ldg + la*16);
            }
        }
        CP_COMMIT();

        int cs = i % STAGES;
        uint32_t aS = sbase + cs*STAGE_BYTES;
        uint32_t bS = aS + 16384;
        #pragma unroll
        for (int kt = 0; kt < 4; kt++) {
            uint32_t af[4][4];
            #pragma unroll
            for (int mt = 0; mt < 4; mt++) {
                int row = wm*64 + mt*16 + (lane & 15);
                int a = kt*2 + (lane >> 4);
                ldsm_x4(af[mt], aS + (uint32_t)row*128 + 16u*(uint32_t)(a ^ (row & 7)));
            }
            uint32_t bf2[2][4];
            #pragma unroll
            for (int np = 0; np < 2; np++) {
                int row = wn*32 + np*16 + ((lane >> 4) & 1)*8 + (lane & 7);
                int a = kt*2 + ((lane >> 3) & 1);
                ldsm_x4(bf2[np], bS + (uint32_t)row*128 + 16u*(uint32_t)(a ^ (row & 7)));
            }
            #pragma unroll
            for (int mt = 0; mt < 4; mt++)
                #pragma unroll
                for (int nt = 0; nt < 4; nt++)
                    mma_any<PREC>(acc[mt][nt], af[mt], bf2[nt>>1][(nt&1)*2], bf2[nt>>1][(nt&1)*2+1]);
        }
    }

    int mW = mBase + wm*64;
    int nW = nBase + wn*32;
    #pragma unroll
    for (int mt = 0; mt < 4; mt++) {
        int r0 = mW + mt*16 + (lane >> 2);
        int r1 = r0 + 8;
        float rs0 = 1.f, rs1 = 1.f;
        if (rowdiv) { rs0 = 1.f / rowdiv[r0]; rs1 = 1.f / rowdiv[r1]; }
        float* c0 = C + (long)r0 * ldc;
        float* c1 = C + (long)r1 * ldc;
        #pragma unroll
        for (int nt = 0; nt < 4; nt++) {
            int cn = nW + nt*8 + 2*(lane & 3);
            const float* dv = acc[mt][nt];
            float w0[2], w1[2];
            #pragma unroll
            for (int e = 0; e < 2; e++) {
                int col = cn + e;
                w0[e] = 0.f; w1[e] = 0.f;
                if (col < N) {
                    float b0 = 0.f;
                    if (act == 2) {
                        int seg = col >> 10;
                        const float* bp = (seg == 0) ? bias : ((seg == 1) ? bias_b : bias_c);
                        b0 = bp[col & 1023];
                    } else if (bias) {
                        b0 = bias[col];
                    }
                    float v0 = dv[e]   * rs0 + b0;
                    float v1 = dv[e+2] * rs1 + b0;
                    bool doelu = (act == 1) || (act == 2 && col < 2048);
                    if (doelu) {
                        v0 = (v0 > 0.f) ? v0 + 1.0f : expf(v0);
                        v1 = (v1 > 0.f) ? v1 + 1.0f : expf(v1);
                    }
                    c0[col] = v0;
                    c1[col] = v1;
                    w0[e] = v0; w1[e] = v1;
                }
            }
            if (Cbf && cn < npk) {
                long g = cn >> 3; int off = cn & 7;
                __align__(4) __nv_bfloat16 t2[2];
                __nv_bfloat16 hA = __float2bfloat16(w0[0]);
                __nv_bfloat16 hB = __float2bfloat16(w0[1]);
                __nv_bfloat16 lA = __float2bfloat16(w0[0] - __bfloat162float(hA));
                __nv_bfloat16 lB = __float2bfloat16(w0[1] - __bfloat162float(hB));
                __nv_bfloat16* p0 = Cbf + (long)r0 * (3*npk) + g*24 + off;
                t2[0] = hA; t2[1] = hB; uint32_t hi0 = *(uint32_t*)t2;
                t2[0] = lA; t2[1] = lB; uint32_t lo0 = *(uint32_t*)t2;
                *(uint32_t*)p0        = hi0;
                *(uint32_t*)(p0 + 8)  = hi0;
                *(uint32_t*)(p0 + 16) = lo0;
                hA = __float2bfloat16(w1[0]);
                hB = __float2bfloat16(w1[1]);
                lA = __float2bfloat16(w1[0] - __bfloat162float(hA));
                lB = __float2bfloat16(w1[1] - __bfloat162float(hB));
                __nv_bfloat16* p1 = Cbf + (long)r1 * (3*npk) + g*24 + off;
                t2[0] = hA; t2[1] = hB; uint32_t hi1 = *(uint32_t*)t2;
                t2[0] = lA; t2[1] = lB; uint32_t lo1 = *(uint32_t*)t2;
                *(uint32_t*)p1        = hi1;
                *(uint32_t*)(p1 + 8)  = hi1;
                *(uint32_t*)(p1 + 16) = lo1;
            }
            if (Chf && cn < npk) {
                __half2 h0 = __floats2half2_rn(w0[0], w0[1]);
                __half2 h1 = __floats2half2_rn(w1[0], w1[1]);
                *(uint32_t*)(Chf + (long)r0 * npk + cn) = *(uint32_t*)&h0;
                *(uint32_t*)(Chf + (long)r1 * npk + cn) = *(uint32_t*)&h1;
            }
        }
    }
}

// ---------------- small kernels ----------------
__global__ void gather_pack(const int* __restrict__ ids,
                            const float* __restrict__ emb,
                            float* __restrict__ x,
                            __nv_bfloat16* __restrict__ xs) {
    int row = blockIdx.x;
    int id  = ids[row];
    int t   = threadIdx.x;       // 0..127
    const float4* src = (const float4*)(emb + (long)id * DMODEL);
    float4* dstx = (float4*)(x + (long)row * DMODEL);
    float4 a = src[2*t], b = src[2*t + 1];
    dstx[2*t] = a; dstx[2*t + 1] = b;
    float xv[8] = {a.x, a.y, a.z, a.w, b.x, b.y, b.z, b.w};
    uint4 hi, lo; split8(xv, &hi, &lo);
    __nv_bfloat16* base = xs + (long)row * K3D + (long)t * 24;
    *(uint4*)(base)      = hi;
    *(uint4*)(base + 8)  = hi;
    *(uint4*)(base + 16) = lo;
}
__global__ void ksum_kernel(const float* __restrict__ src, int ld, long zstride,
                            float* __restrict__ ks) {
    int d = blockIdx.x * 256 + threadIdx.x;
    int b = blockIdx.y;
    const float* p = src + (long)b * zstride + d;
    float acc = 0.f;
    #pragma unroll 8
    for (int n = 0; n < NSEQ; n++) acc += p[(long)n * ld];
    ks[b * DMODEL + d] = acc + EPS_F;
}
__global__ void z_kernel(const float* __restrict__ Q, int ld,
                         const float* __restrict__ ks, float* __restrict__ z) {
    int row  = blockIdx.x * 8 + (threadIdx.x >> 5);
    int lane = threadIdx.x & 31;
    int b    = row / NSEQ;
    const float* q = Q  + (long)row * ld;
    const float* s = ks + (long)b   * DMODEL;
    float acc = 0.f;
    #pragma unroll 4
    for (int i = lane; i < DMODEL; i += 32) acc += q[i] * s[i];
    #pragma unroll
    for (int o = 16; o; o >>= 1) acc += __shfl_xor_sync(0xffffffffu, acc, o);
    if (lane == 0) z[row] = acc;
}
__global__ void pooled_kernel(const float* __restrict__ x, float* __restrict__ out) {
    int i = blockIdx.x * blockDim.x + threadIdx.x;
    if (i >= BATCH * DMODEL) return;
    int b = i / DMODEL, d = i % DMODEL;
    out[i] = x[((long)b * NSEQ + (NSEQ - 1)) * DMODEL + d];
}

// ---------------- driver ----------------
static inline long cdivl(long a, long b){ return (a + b - 1) / b; }

extern "C" void kernel_launch(void* const* d_in, const int* in_sizes, int n_in,
                              void* d_out, int out_size) {
    const int*   ids = (const int*)  d_in[0];
    const float* emb = (const float*)d_in[1];
    const float* Wq  = (const float*)d_in[2];
    const float* bq  = (const float*)d_in[3];
    const float* Wk  = (const float*)d_in[4];
    const float* bk  = (const float*)d_in[5];
    const float* Wv  = (const float*)d_in[6];
    const float* bv  = (const float*)d_in[7];
    const float* Wo  = (const float*)d_in[8];
    const float* bo  = (const float*)d_in[9];
    const float* Wh  = (const float*)d_in[10];
    const float* bh  = (const float*)d_in[11];

    float* logits = (float*)d_out;
    float* pooled = logits + (long)MTOK * VOCAB;

    float *x, *qkv, *part, *ks, *z;
    __nv_bfloat16 *xs, *qs, *kts, *vts, *wbuf, *Wsp, *wos, *whs;
    cudaGetSymbolAddress((void**)&x,    g_x);
    cudaGetSymbolAddress((void**)&qkv,  g_qkv);
    cudaGetSymbolAddress((void**)&part, g_part);
    cudaGetSymbolAddress((void**)&ks,   g_ks);
    cudaGetSymbolAddress((void**)&z,    g_z);
    cudaGetSymbolAddress((void**)&xs,   g_xs);
    cudaGetSymbolAddress((void**)&qs,   g_qs);
    cudaGetSymbolAddress((void**)&kts,  g_kts);
    cudaGetSymbolAddress((void**)&vts,  g_vts);
    cudaGetSymbolAddress((void**)&wbuf, g_wbuf);
    cudaGetSymbolAddress((void**)&Wsp,  g_Wsp);
    cudaGetSymbolAddress((void**)&wos,  g_wos);
    cudaGetSymbolAddress((void**)&whs,  g_whs);

    cudaFuncSetAttribute(hgemm_kernel<0>, cudaFuncAttributeMaxDynamicSharedMemorySize, GEMM_SMEM);
    cudaFuncSetAttribute(hgemm_kernel<1>, cudaFuncAttributeMaxDynamicSharedMemorySize, GEMM_SMEM);

    const long sTok = (long)NSEQ * DMODEL;
    const long sW   = (long)DMODEL * DMODEL;
    const long wTU  = (long)DMODEL * (DMODEL/8);
    const long zQKV = (long)NSEQ * QKVLD;
    const long sKts = (long)DMODEL * K3N;
    const long sWsp = (long)DMODEL * K3D;

    gather_pack<<<MTOK, 128>>>(ids, emb, x, xs);

    for (int l = 0; l < NLAYER; l++) {
        const float* wq = Wq + (long)l * sW;
        const float* wk = Wk + (long)l * sW;
        const float* wv = Wv + (long)l * sW;
        const float* wo = Wo + (long)l * sW;
        const float* bql = bq + (long)l * DMODEL;
        const float* bkl = bk + (long)l * DMODEL;
        const float* bvl = bv + (long)l * DMODEL;
        const float* bol = bo + (long)l * DMODEL;
        bool last = (l == NLAYER - 1);

        pack_b3<<<dim3(512, 3), 256>>>(wq, wk, wv, wbuf);

        // fused QKV GEMM; epilogue also emits packed Q panel (qs)
        hgemm_kernel<0><<<dim3(32, 24, 1), 256, GEMM_SMEM>>>(xs, wbuf, 0, 0, K3D, K3D, 3*DMODEL,
            qkv, QKVLD, 0, bql, bkl, bvl, nullptr, 0, 2,
            qs, 0, nullptr, 0, DMODEL, 1);

        {
            dim3 gT(DMODEL/32, NSEQ/64, BATCH);
            pack_trans_tiled<true ><<<gT, 256>>>(qkv + DMODEL,   QKVLD, NSEQ, kts, zQKV, sKts);
            pack_trans_tiled<false><<<gT, 256>>>(qkv + 2*DMODEL, QKVLD, NSEQ, vts, zQKV, sKts);
        }
        // W2[d,e] = sum_n K[n,d] V[n,e]  -- split-K x4 (512 CTAs)
        hgemm_kernel<0><<<dim3(8, 8, BATCH*4), 256, GEMM_SMEM>>>(kts, vts,
            sKts, sKts, K3N, K3N/4, DMODEL, part, DMODEL, MNW,
            nullptr, nullptr, nullptr, nullptr, 0, 0,
            nullptr, 0, nullptr, 0, 0, 4);

        ksum_kernel<<<dim3(DMODEL/256, BATCH), 256>>>(qkv + DMODEL, QKVLD, zQKV, ks);
        z_kernel<<<MTOK/8, 256>>>(qkv, QKVLD, ks, z);

        pack_a_direct<<<(unsigned)cdivl(wTU,256), 256>>>(wo, DMODEL, DMODEL, DMODEL, wos);
        // reduce W2 partials + pack as B'
        pack_b_sum<<<dim3(512, BATCH), 256>>>(part, 4, Wsp, sWsp);
        // G[i,d] = sum_e Wo[i,e] W2[d,e]  -- split-K x2 (256 CTAs)
        hgemm_kernel<0><<<dim3(8, 8, BATCH*2), 256, GEMM_SMEM>>>(wos, Wsp,
            0, sWsp, K3D, K3D/2, DMODEL, part, DMODEL, MNW,
            nullptr, nullptr, nullptr, nullptr, 0, 0,
            nullptr, 0, nullptr, 0, 0, 2);
        // reduce G partials + pack as B' (vts reused as Gsp)
        pack_b_sum<<<dim3(512, BATCH), 256>>>(part, 2, vts, sWsp);
        // x = (Q . G^T)/Z + bo ; epilogue emits next-layer xs and (last) fp16 head x
        hgemm_kernel<0><<<dim3(16, 8, BATCH), 256, GEMM_SMEM>>>(qs, vts,
            (long)NSEQ*K3D, sWsp, K3D, K3D, DMODEL, x, DMODEL, sTok,
            bol, nullptr, nullptr, z, NSEQ, 0,
            xs, (long)NSEQ*K3D, last ? (__half*)wbuf : nullptr, (long)NSEQ*DMODEL, DMODEL, 1);
    }

    // head: logits = fp16(x) @ fp16(Wh)^T + bh
    {
        long total = (long)NPAD_H * 64;
        cvt_fp16_fast<<<(unsigned)cdivl(total,256), 256>>>(Wh, VOCAB, NPAD_H, (__half*)whs);
        hgemm_kernel<1><<<dim3(32, NTILES_H, 1), 256, GEMM_SMEM>>>(wbuf, whs, 0, 0, DMODEL, DMODEL, VOCAB,
            logits, VOCAB, 0, bh, nullptr, nullptr, nullptr, 0, 0,
            nullptr, 0, nullptr, 0, 0, 1);
    }

    pooled_kernel<<<(BATCH * DMODEL + 255) / 256, 256>>>(x, pooled);
}